// round 7
// baseline (speedup 1.0000x reference)
#include <cuda_runtime.h>
#include <cuda_bf16.h>

#define BB 2
#define NN 1024
#define DD 16
#define HH 8
#define W1STRIDE (3 * DD + 1)   // 49

typedef unsigned long long ull;

__device__ __forceinline__ float tanh_approx(float x) {
    float y;
    asm("tanh.approx.f32 %0, %1;" : "=f"(y) : "f"(x));
    return y;
}
__device__ __forceinline__ ull pack2(float lo, float hi) {
    ull d;
    asm("mov.b64 %0, {%1, %2};" : "=l"(d) : "f"(lo), "f"(hi));
    return d;
}
__device__ __forceinline__ void unpack2(ull v, float& lo, float& hi) {
    asm("mov.b64 {%0, %1}, %2;" : "=f"(lo), "=f"(hi) : "l"(v));
}
__device__ __forceinline__ ull fma2(ull a, ull b, ull c) {
    ull d;
    asm("fma.rn.f32x2 %0, %1, %2, %3;" : "=l"(d) : "l"(a), "l"(b), "l"(c));
    return d;
}
__device__ __forceinline__ ull add2(ull a, ull b) {
    ull d;
    asm("add.rn.f32x2 %0, %1, %2;" : "=l"(d) : "l"(a), "l"(b));
    return d;
}

// ---------------------------------------------------------------------------
// Fused kernel, h-pair packing. Block = 256 threads = 32 i x 8 j-quads;
// 4 edges/thread. Activations packed as (h_even, h_odd) f32x2 pairs, so
// layer weights are consumed in natural row-major [k][h] layout via
// LDS.128 with NO duplication: 16 weight LDS.128 per layer instead of 32.
// ---------------------------------------------------------------------------
__global__ __launch_bounds__(256, 3)
void edge_mlp_kernel(const float* __restrict__ x,
                     const float* __restrict__ A,
                     const float* __restrict__ vp,
                     const float* __restrict__ W1, const float* __restrict__ b1,
                     const float* __restrict__ W2, const float* __restrict__ b2,
                     const float* __restrict__ W3, const float* __restrict__ b3,
                     const float* __restrict__ W4, const float* __restrict__ b4,
                     const float* __restrict__ W5, const float* __restrict__ b5,
                     float* __restrict__ out) {
    __shared__ __align__(16) float s_xj[32][DD];
    __shared__ __align__(16) float s_xi[32][DD];
    __shared__ __align__(16) float s_w1[HH * W1STRIDE];
    __shared__ __align__(16) float s_tj[32][HH];    // [j][h]
    __shared__ __align__(16) float s_ti[32][HH];    // [i][h], incl. t_v + b1
    __shared__ __align__(16) float s_w234[3][HH * HH];  // raw row-major [k][h]
    __shared__ __align__(16) float s_b234[3][HH];
    __shared__ __align__(16) float s_w5[HH];
    __shared__ __align__(16) float s_wa[HH];        // W1[:,48]
    __shared__ __align__(16) float s_vp[DD];
    __shared__ __align__(16) float s_b1[HH];
    __shared__ float s_b5;

    const int tid = threadIdx.x;
    const int b  = blockIdx.z;
    const int i0 = blockIdx.y * 32;
    const int j0 = blockIdx.x * 32;

    // --- phase 1: stage everything into shared ---
    {
        int row = tid >> 2;
        int c4  = (tid & 3) * 4;
        if (row < 32) {
            float4 v = *reinterpret_cast<const float4*>(x + ((size_t)(b * NN + j0 + row)) * DD + c4);
            s_xj[row][c4] = v.x; s_xj[row][c4 + 1] = v.y;
            s_xj[row][c4 + 2] = v.z; s_xj[row][c4 + 3] = v.w;
        } else {
            int r = row - 32;
            float4 v = *reinterpret_cast<const float4*>(x + ((size_t)(b * NN + i0 + r)) * DD + c4);
            s_xi[r][c4] = v.x; s_xi[r][c4 + 1] = v.y;
            s_xi[r][c4 + 2] = v.z; s_xi[r][c4 + 3] = v.w;
        }
        s_w1[tid] = W1[tid];
        if (tid < HH * W1STRIDE - 256) s_w1[256 + tid] = W1[256 + tid];
        if (tid < 64) {
            s_w234[0][tid] = W2[tid];
            s_w234[1][tid] = W3[tid];
            s_w234[2][tid] = W4[tid];
        }
        if (tid < DD) s_vp[tid] = vp[b * DD + tid];
        if (tid < 8) {
            s_b234[0][tid] = b2[tid];
            s_b234[1][tid] = b3[tid];
            s_b234[2][tid] = b4[tid];
            s_w5[tid] = W5[tid];
            s_wa[tid] = W1[tid * W1STRIDE + 3 * DD];
            s_b1[tid] = b1[tid];
        }
        if (tid == 0) s_b5 = b5[0];
    }
    __syncthreads();

    const int ii = tid >> 3;         // 0..31
    const int jl = (tid & 7) * 4;    // 0,4,...,28

    // Early global A load
    const size_t off = ((size_t)(b * NN + i0 + ii)) * NN + j0 + jl;
    float4 a4 = *reinterpret_cast<const float4*>(A + off);

    // --- phase 2: per-row projections (one (n,h) pair per thread) ---
    {
        int n = tid >> 3;
        int h = tid & 7;
        const float* wr = s_w1 + h * W1STRIDE;
        float tj = 0.0f, ti = 0.0f, tv = s_b1[h];
#pragma unroll
        for (int c = 0; c < DD; c++) {
            tj += s_xj[n][c] * wr[c];
            ti += s_xi[n][c] * wr[DD + c];
            tv += s_vp[c]    * wr[2 * DD + c];
        }
        s_tj[n][h] = tj;
        s_ti[n][h] = ti + tv;
    }
    __syncthreads();

    // --- phase 3: edge MLP with h-pair packing ---
    float a[4] = { a4.x, a4.y, a4.z, a4.w };

    // layer-1 operands shared across edges
    ull ti2[4], wa2[4];
    {
        ulonglong2 t0 = *reinterpret_cast<const ulonglong2*>(&s_ti[ii][0]);
        ulonglong2 t1 = *reinterpret_cast<const ulonglong2*>(&s_ti[ii][4]);
        ti2[0] = t0.x; ti2[1] = t0.y; ti2[2] = t1.x; ti2[3] = t1.y;
        ulonglong2 w0 = *reinterpret_cast<const ulonglong2*>(&s_wa[0]);
        ulonglong2 w1v = *reinterpret_cast<const ulonglong2*>(&s_wa[4]);
        wa2[0] = w0.x; wa2[1] = w0.y; wa2[2] = w1v.x; wa2[3] = w1v.y;
    }

    // layer 1: h2[e][hp] = tanh pairs
    ull h2[4][4];
#pragma unroll
    for (int e = 0; e < 4; e++) {
        ulonglong2 tA = *reinterpret_cast<const ulonglong2*>(&s_tj[jl + e][0]);
        ulonglong2 tB = *reinterpret_cast<const ulonglong2*>(&s_tj[jl + e][4]);
        ull ae = pack2(a[e], a[e]);
        ull p0 = fma2(ae, wa2[0], add2(tA.x, ti2[0]));
        ull p1 = fma2(ae, wa2[1], add2(tA.y, ti2[1]));
        ull p2 = fma2(ae, wa2[2], add2(tB.x, ti2[2]));
        ull p3 = fma2(ae, wa2[3], add2(tB.y, ti2[3]));
        float u0, u1, v0, v1, w0, w1, z0, z1;
        unpack2(p0, u0, u1); unpack2(p1, v0, v1);
        unpack2(p2, w0, w1); unpack2(p3, z0, z1);
        h2[e][0] = pack2(tanh_approx(u0), tanh_approx(u1));
        h2[e][1] = pack2(tanh_approx(v0), tanh_approx(v1));
        h2[e][2] = pack2(tanh_approx(w0), tanh_approx(w1));
        h2[e][3] = pack2(tanh_approx(z0), tanh_approx(z1));
    }

    // layers 2..4: weights consumed raw row-major via h-pairs
#pragma unroll
    for (int l = 0; l < 3; l++) {
        float bk[HH];
        {
            float4 bA = *reinterpret_cast<const float4*>(&s_b234[l][0]);
            float4 bB = *reinterpret_cast<const float4*>(&s_b234[l][4]);
            bk[0] = bA.x; bk[1] = bA.y; bk[2] = bA.z; bk[3] = bA.w;
            bk[4] = bB.x; bk[5] = bB.y; bk[6] = bB.z; bk[7] = bB.w;
        }
        ull nh[4][4];
#pragma unroll
        for (int kp = 0; kp < 4; kp++) {
            float t[4][2];
#pragma unroll
            for (int half = 0; half < 2; half++) {
                int k = kp * 2 + half;
                const float* wr = &s_w234[l][k * HH];
                ulonglong2 wlo = *reinterpret_cast<const ulonglong2*>(wr);
                ulonglong2 whi = *reinterpret_cast<const ulonglong2*>(wr + 4);
                ull bini = pack2(bk[k], 0.0f);   // hoisted, shared by 4 edges
#pragma unroll
                for (int e = 0; e < 4; e++) {
                    ull p = fma2(h2[e][0], wlo.x, bini);
                    p = fma2(h2[e][1], wlo.y, p);
                    p = fma2(h2[e][2], whi.x, p);
                    p = fma2(h2[e][3], whi.y, p);
                    float lo, hi;
                    unpack2(p, lo, hi);
                    t[e][half] = tanh_approx(lo + hi);
                }
            }
#pragma unroll
            for (int e = 0; e < 4; e++)
                nh[e][kp] = pack2(t[e][0], t[e][1]);
        }
#pragma unroll
        for (int e = 0; e < 4; e++)
#pragma unroll
            for (int kp = 0; kp < 4; kp++)
                h2[e][kp] = nh[e][kp];
    }

    // output layer: w5 as h-pairs, horizontal add + b5
    ull w52[4];
    {
        ulonglong2 w0 = *reinterpret_cast<const ulonglong2*>(&s_w5[0]);
        ulonglong2 w1v = *reinterpret_cast<const ulonglong2*>(&s_w5[4]);
        w52[0] = w0.x; w52[1] = w0.y; w52[2] = w1v.x; w52[3] = w1v.y;
    }
    float b5v = s_b5;
    float o[4];
#pragma unroll
    for (int e = 0; e < 4; e++) {
        ull p = fma2(h2[e][0], w52[0], pack2(b5v, 0.0f));
        p = fma2(h2[e][1], w52[1], p);
        p = fma2(h2[e][2], w52[2], p);
        p = fma2(h2[e][3], w52[3], p);
        float lo, hi;
        unpack2(p, lo, hi);
        o[e] = lo + hi;
    }
    *reinterpret_cast<float4*>(out + off) = make_float4(o[0], o[1], o[2], o[3]);
}

// ---------------------------------------------------------------------------
extern "C" void kernel_launch(void* const* d_in, const int* in_sizes, int n_in,
                              void* d_out, int out_size) {
    const float* x  = (const float*)d_in[0];
    const float* A  = (const float*)d_in[1];
    const float* vp = (const float*)d_in[2];
    const float* W1 = (const float*)d_in[3];
    const float* b1 = (const float*)d_in[4];
    const float* W2 = (const float*)d_in[5];
    const float* b2 = (const float*)d_in[6];
    const float* W3 = (const float*)d_in[7];
    const float* b3 = (const float*)d_in[8];
    const float* W4 = (const float*)d_in[9];
    const float* b4 = (const float*)d_in[10];
    const float* W5 = (const float*)d_in[11];
    const float* b5 = (const float*)d_in[12];
    float* out = (float*)d_out;

    dim3 grid(NN / 32, NN / 32, BB);   // 32 x 32 x 2 = 2048 blocks
    edge_mlp_kernel<<<grid, 256>>>(x, A, vp, W1, b1, W2, b2, W3, b3,
                                   W4, b4, W5, b5, out);
}

// round 8
// speedup vs baseline: 1.0088x; 1.0088x over previous
#include <cuda_runtime.h>
#include <cuda_bf16.h>

#define BB 2
#define NN 1024
#define DD 16
#define HH 8
#define W1STRIDE (3 * DD + 1)   // 49

typedef unsigned long long ull;

__device__ __forceinline__ float tanh_approx(float x) {
    float y;
    asm("tanh.approx.f32 %0, %1;" : "=f"(y) : "f"(x));
    return y;
}
__device__ __forceinline__ ull pack2(float lo, float hi) {
    ull d;
    asm("mov.b64 %0, {%1, %2};" : "=l"(d) : "f"(lo), "f"(hi));
    return d;
}
__device__ __forceinline__ void unpack2(ull v, float& lo, float& hi) {
    asm("mov.b64 {%0, %1}, %2;" : "=f"(lo), "=f"(hi) : "l"(v));
}
__device__ __forceinline__ ull fma2(ull a, ull b, ull c) {
    ull d;
    asm("fma.rn.f32x2 %0, %1, %2, %3;" : "=l"(d) : "l"(a), "l"(b), "l"(c));
    return d;
}
__device__ __forceinline__ ull add2(ull a, ull b) {
    ull d;
    asm("add.rn.f32x2 %0, %1, %2;" : "=l"(d) : "l"(a), "l"(b));
    return d;
}
__device__ __forceinline__ ull tanh2(ull v) {
    float lo, hi;
    unpack2(v, lo, hi);
    return pack2(tanh_approx(lo), tanh_approx(hi));
}

// ---------------------------------------------------------------------------
// Fused kernel, register-lean: tile = 32 i x 16 j per block (256 threads);
// each thread computes 2 edges (one f32x2 lane). Core live set = 16 ulls so
// 4 CTAs/SM fit at <=64 regs (launch_bounds(256,4)) -> 32 warps/SM.
// Edge-packed lanes + dup-pair weight tables [h][k] (R5 dataflow).
// ---------------------------------------------------------------------------
__global__ __launch_bounds__(256, 4)
void edge_mlp_kernel(const float* __restrict__ x,
                     const float* __restrict__ A,
                     const float* __restrict__ vp,
                     const float* __restrict__ W1, const float* __restrict__ b1,
                     const float* __restrict__ W2, const float* __restrict__ b2,
                     const float* __restrict__ W3, const float* __restrict__ b3,
                     const float* __restrict__ W4, const float* __restrict__ b4,
                     const float* __restrict__ W5, const float* __restrict__ b5,
                     float* __restrict__ out) {
    __shared__ __align__(16) float s_xj[16][DD];      // x rows for j tile
    __shared__ __align__(16) float s_xi[32][DD];      // x rows for i tile
    __shared__ __align__(16) float s_w1[HH * W1STRIDE];
    __shared__ __align__(16) float s_tjt[HH][16];     // t_j transposed [h][j]
    __shared__ __align__(16) float s_ti[32][HH];      // t_i + t_v + b1
    __shared__ __align__(16) ull   s_wd[3][HH * HH];  // W-l transposed [h][k], dup pairs
    __shared__ __align__(16) ull   s_bd[3][HH];       // biases dup pairs
    __shared__ __align__(16) ull   s_w5d[HH];
    __shared__ __align__(16) ull   s_w1ad[HH];
    __shared__ float s_vp[DD];
    __shared__ float s_b1[HH];
    __shared__ ull   s_b5d;

    const int tid = threadIdx.x;
    const int b  = blockIdx.z;
    const int i0 = blockIdx.y * 32;
    const int j0 = blockIdx.x * 16;

    // --- phase 1: stage x rows + all weights into shared ---
    {
        // 48 rows x 4 float4 = 192 float4 loads (threads 0..191)
        if (tid < 192) {
            int r  = tid >> 2;
            int c4 = (tid & 3) * 4;
            if (r < 16) {
                float4 v = *reinterpret_cast<const float4*>(
                    x + ((size_t)(b * NN + j0 + r)) * DD + c4);
                s_xj[r][c4] = v.x; s_xj[r][c4 + 1] = v.y;
                s_xj[r][c4 + 2] = v.z; s_xj[r][c4 + 3] = v.w;
            } else {
                int rr = r - 16;
                float4 v = *reinterpret_cast<const float4*>(
                    x + ((size_t)(b * NN + i0 + rr)) * DD + c4);
                s_xi[rr][c4] = v.x; s_xi[rr][c4 + 1] = v.y;
                s_xi[rr][c4 + 2] = v.z; s_xi[rr][c4 + 3] = v.w;
            }
        }
        s_w1[tid] = W1[tid];
        if (tid < HH * W1STRIDE - 256) s_w1[256 + tid] = W1[256 + tid];
        if (tid < 64) {
            int dstT = (tid & 7) * HH + (tid >> 3);   // [k][h] -> [h][k]
            float w2 = W2[tid], w3 = W3[tid], w4 = W4[tid];
            s_wd[0][dstT] = pack2(w2, w2);
            s_wd[1][dstT] = pack2(w3, w3);
            s_wd[2][dstT] = pack2(w4, w4);
        }
        if (tid < DD) s_vp[tid] = vp[b * DD + tid];
        if (tid < 8) {
            float v2 = b2[tid], v3 = b3[tid], v4 = b4[tid];
            s_bd[0][tid] = pack2(v2, v2);
            s_bd[1][tid] = pack2(v3, v3);
            s_bd[2][tid] = pack2(v4, v4);
            float w5 = W5[tid];
            s_w5d[tid] = pack2(w5, w5);
            float wa = W1[tid * W1STRIDE + 3 * DD];
            s_w1ad[tid] = pack2(wa, wa);
            s_b1[tid] = b1[tid];
        }
        if (tid == 0) { float v = b5[0]; s_b5d = pack2(v, v); }
    }
    __syncthreads();

    const int ii = tid >> 3;         // 0..31
    const int jl = (tid & 7) * 2;    // 0,2,...,14

    // Early global A load (float2, coalesced)
    const size_t off = ((size_t)(b * NN + i0 + ii)) * NN + j0 + jl;
    float2 a2f = *reinterpret_cast<const float2*>(A + off);

    // --- phase 2: per-row projections ---
    {
        int n = tid >> 3;      // 0..31
        int h = tid & 7;
        const float* wr = s_w1 + h * W1STRIDE;
        float ti = 0.0f, tv = s_b1[h];
#pragma unroll
        for (int c = 0; c < DD; c++) {
            ti += s_xi[n][c] * wr[DD + c];
            tv += s_vp[c]    * wr[2 * DD + c];
        }
        s_ti[n][h] = ti + tv;
        if (n < 16) {
            float tj = 0.0f;
#pragma unroll
            for (int c = 0; c < DD; c++)
                tj += s_xj[n][c] * wr[c];
            s_tjt[h][n] = tj;
        }
    }
    __syncthreads();

    // --- phase 3: packed edge MLP, one f32x2 lane (2 edges) ---
    ull av = pack2(a2f.x, a2f.y);

    // layer 1
    ull h2[HH];
#pragma unroll
    for (int h = 0; h < HH; h++) {
        ull tj2 = *reinterpret_cast<const ull*>(&s_tjt[h][jl]);
        float tival = s_ti[ii][h];
        ull pre = fma2(av, s_w1ad[h], add2(tj2, pack2(tival, tival)));
        h2[h] = tanh2(pre);
    }

    // layers 2..4: h outer, k inner; 8 independent acc chains
#pragma unroll
    for (int l = 0; l < 3; l++) {
        ull acc[HH];
#pragma unroll
        for (int k = 0; k < HH; k += 2) {
            ulonglong2 bk = *reinterpret_cast<const ulonglong2*>(&s_bd[l][k]);
            acc[k] = bk.x;
            acc[k + 1] = bk.y;
        }
#pragma unroll
        for (int h = 0; h < HH; h++) {
            ull hv = h2[h];
#pragma unroll
            for (int kp = 0; kp < HH / 2; kp++) {
                ulonglong2 w = *reinterpret_cast<const ulonglong2*>(&s_wd[l][h * HH + kp * 2]);
                acc[kp * 2]     = fma2(hv, w.x, acc[kp * 2]);
                acc[kp * 2 + 1] = fma2(hv, w.y, acc[kp * 2 + 1]);
            }
        }
#pragma unroll
        for (int k = 0; k < HH; k++)
            h2[k] = tanh2(acc[k]);
    }

    // output layer
    ull o2 = s_b5d;
#pragma unroll
    for (int h = 0; h < HH; h++)
        o2 = fma2(h2[h], s_w5d[h], o2);
    float2 o;
    unpack2(o2, o.x, o.y);
    *reinterpret_cast<float2*>(out + off) = o;
}

// ---------------------------------------------------------------------------
extern "C" void kernel_launch(void* const* d_in, const int* in_sizes, int n_in,
                              void* d_out, int out_size) {
    const float* x  = (const float*)d_in[0];
    const float* A  = (const float*)d_in[1];
    const float* vp = (const float*)d_in[2];
    const float* W1 = (const float*)d_in[3];
    const float* b1 = (const float*)d_in[4];
    const float* W2 = (const float*)d_in[5];
    const float* b2 = (const float*)d_in[6];
    const float* W3 = (const float*)d_in[7];
    const float* b3 = (const float*)d_in[8];
    const float* W4 = (const float*)d_in[9];
    const float* b4 = (const float*)d_in[10];
    const float* W5 = (const float*)d_in[11];
    const float* b5 = (const float*)d_in[12];
    float* out = (float*)d_out;

    dim3 grid(NN / 16, NN / 32, BB);   // 64 x 32 x 2 = 4096 blocks
    edge_mlp_kernel<<<grid, 256>>>(x, A, vp, W1, b1, W2, b2, W3, b3,
                                   W4, b4, W5, b5, out);
}

// round 9
// speedup vs baseline: 1.1057x; 1.0960x over previous
#include <cuda_runtime.h>
#include <cuda_bf16.h>

#define BB 2
#define NN 1024
#define DD 16
#define HH 8
#define W1STRIDE (3 * DD + 1)   // 49

typedef unsigned long long ull;

__device__ __forceinline__ float tanh_approx(float x) {
    float y;
    asm("tanh.approx.f32 %0, %1;" : "=f"(y) : "f"(x));
    return y;
}
__device__ __forceinline__ ull pack2(float lo, float hi) {
    ull d;
    asm("mov.b64 %0, {%1, %2};" : "=l"(d) : "f"(lo), "f"(hi));
    return d;
}
__device__ __forceinline__ void unpack2(ull v, float& lo, float& hi) {
    asm("mov.b64 {%0, %1}, %2;" : "=f"(lo), "=f"(hi) : "l"(v));
}
__device__ __forceinline__ ull fma2(ull a, ull b, ull c) {
    ull d;
    asm("fma.rn.f32x2 %0, %1, %2, %3;" : "=l"(d) : "l"(a), "l"(b), "l"(c));
    return d;
}
__device__ __forceinline__ ull add2(ull a, ull b) {
    ull d;
    asm("add.rn.f32x2 %0, %1, %2;" : "=l"(d) : "l"(a), "l"(b));
    return d;
}
__device__ __forceinline__ ull tanh2(ull v) {
    float lo, hi;
    unpack2(v, lo, hi);
    return pack2(tanh_approx(lo), tanh_approx(hi));
}
__device__ __forceinline__ float dot4(float4 a, float4 b) {
    return a.x * b.x + a.y * b.y + a.z * b.z + a.w * b.w;
}

// ---------------------------------------------------------------------------
// R5 dataflow (32i x 32j tile, 4 edges/thread as 2 f32x2 lanes, dup-pair
// weight tables [h][k]) with fully vectorized LDS: phase-2 projections and
// phase-3 small-vector reads all go through LDS.128.
// ---------------------------------------------------------------------------
__global__ __launch_bounds__(256, 3)
void edge_mlp_kernel(const float* __restrict__ x,
                     const float* __restrict__ A,
                     const float* __restrict__ vp,
                     const float* __restrict__ W1, const float* __restrict__ b1,
                     const float* __restrict__ W2, const float* __restrict__ b2,
                     const float* __restrict__ W3, const float* __restrict__ b3,
                     const float* __restrict__ W4, const float* __restrict__ b4,
                     const float* __restrict__ W5, const float* __restrict__ b5,
                     float* __restrict__ out) {
    __shared__ __align__(16) float s_xj[32][DD];
    __shared__ __align__(16) float s_xi[32][DD];
    __shared__ __align__(16) float s_w1j[HH][DD];     // W1[:, 0:16]
    __shared__ __align__(16) float s_w1i[HH][DD];     // W1[:, 16:32]
    __shared__ __align__(16) float s_w1v[HH][DD];     // W1[:, 32:48]
    __shared__ __align__(16) float s_tjt[HH][32];     // t_j transposed [h][j]
    __shared__ __align__(16) float s_ti[32][HH];      // t_i + t_v + b1
    __shared__ __align__(16) ull   s_wd[3][HH * HH];  // W-l transposed [h][k], dup pairs
    __shared__ __align__(16) ull   s_bd[3][HH];       // biases dup pairs
    __shared__ __align__(16) ull   s_w5d[HH];
    __shared__ __align__(16) ull   s_w1ad[HH];
    __shared__ __align__(16) float s_vp[DD];
    __shared__ __align__(16) float s_b1[HH];
    __shared__ ull   s_b5d;

    const int tid = threadIdx.x;
    const int b  = blockIdx.z;
    const int i0 = blockIdx.y * 32;
    const int j0 = blockIdx.x * 32;

    // --- phase 1: stage x rows + all weights into shared ---
    {
        int row = tid >> 2;
        int c4  = (tid & 3) * 4;
        if (row < 32) {
            float4 v = *reinterpret_cast<const float4*>(x + ((size_t)(b * NN + j0 + row)) * DD + c4);
            s_xj[row][c4] = v.x; s_xj[row][c4 + 1] = v.y;
            s_xj[row][c4 + 2] = v.z; s_xj[row][c4 + 3] = v.w;
        } else {
            int r = row - 32;
            float4 v = *reinterpret_cast<const float4*>(x + ((size_t)(b * NN + i0 + r)) * DD + c4);
            s_xi[r][c4] = v.x; s_xi[r][c4 + 1] = v.y;
            s_xi[r][c4 + 2] = v.z; s_xi[r][c4 + 3] = v.w;
        }
        // scatter W1 into aligned sub-arrays (c==48 handled by the tid<8 path)
        for (int g = tid; g < HH * W1STRIDE; g += 256) {
            int h = g / W1STRIDE;
            int c = g - h * W1STRIDE;
            float w = W1[g];
            if (c < DD)          s_w1j[h][c]          = w;
            else if (c < 2 * DD) s_w1i[h][c - DD]     = w;
            else if (c < 3 * DD) s_w1v[h][c - 2 * DD] = w;
        }
        if (tid < 64) {
            int dstT = (tid & 7) * HH + (tid >> 3);   // [k][h] -> [h][k]
            float w2 = W2[tid], w3 = W3[tid], w4 = W4[tid];
            s_wd[0][dstT] = pack2(w2, w2);
            s_wd[1][dstT] = pack2(w3, w3);
            s_wd[2][dstT] = pack2(w4, w4);
        }
        if (tid < DD) s_vp[tid] = vp[b * DD + tid];
        if (tid < 8) {
            float v2 = b2[tid], v3 = b3[tid], v4 = b4[tid];
            s_bd[0][tid] = pack2(v2, v2);
            s_bd[1][tid] = pack2(v3, v3);
            s_bd[2][tid] = pack2(v4, v4);
            float w5 = W5[tid];
            s_w5d[tid] = pack2(w5, w5);
            float wa = W1[tid * W1STRIDE + 3 * DD];
            s_w1ad[tid] = pack2(wa, wa);
            s_b1[tid] = b1[tid];
        }
        if (tid == 0) { float v = b5[0]; s_b5d = pack2(v, v); }
    }
    __syncthreads();

    const int ii = tid >> 3;         // 0..31
    const int jl = (tid & 7) * 4;    // 0,4,...,28

    // Early global A load to overlap with phase 2
    const size_t off = ((size_t)(b * NN + i0 + ii)) * NN + j0 + jl;
    float4 a4 = *reinterpret_cast<const float4*>(A + off);

    // --- phase 2: per-row projections, fully float4-vectorized ---
    {
        int n = tid >> 3;
        int h = tid & 7;
        const float4* xj4 = reinterpret_cast<const float4*>(&s_xj[n][0]);
        const float4* xi4 = reinterpret_cast<const float4*>(&s_xi[n][0]);
        const float4* wj4 = reinterpret_cast<const float4*>(&s_w1j[h][0]);
        const float4* wi4 = reinterpret_cast<const float4*>(&s_w1i[h][0]);
        const float4* wv4 = reinterpret_cast<const float4*>(&s_w1v[h][0]);
        const float4* vp4 = reinterpret_cast<const float4*>(&s_vp[0]);
        float tj = 0.0f, ti = 0.0f, tv = s_b1[h];
#pragma unroll
        for (int q = 0; q < 4; q++) {
            tj += dot4(xj4[q], wj4[q]);
            ti += dot4(xi4[q], wi4[q]);
            tv += dot4(vp4[q], wv4[q]);
        }
        s_tjt[h][n] = tj;
        s_ti[n][h]  = ti + tv;
    }
    __syncthreads();

    // --- phase 3: packed edge MLP (2 f32x2 lanes = 4 edges) ---
    ull a2lo = pack2(a4.x, a4.y);
    ull a2hi = pack2(a4.z, a4.w);

    // t_i and W1_A pulled in via LDS.128
    float4 ti03 = *reinterpret_cast<const float4*>(&s_ti[ii][0]);
    float4 ti47 = *reinterpret_cast<const float4*>(&s_ti[ii][4]);
    float tiv[HH] = { ti03.x, ti03.y, ti03.z, ti03.w,
                      ti47.x, ti47.y, ti47.z, ti47.w };
    ull wa[HH];
    {
        ulonglong2 w0 = *reinterpret_cast<const ulonglong2*>(&s_w1ad[0]);
        ulonglong2 w1v = *reinterpret_cast<const ulonglong2*>(&s_w1ad[2]);
        ulonglong2 w2v = *reinterpret_cast<const ulonglong2*>(&s_w1ad[4]);
        ulonglong2 w3v = *reinterpret_cast<const ulonglong2*>(&s_w1ad[6]);
        wa[0] = w0.x; wa[1] = w0.y; wa[2] = w1v.x; wa[3] = w1v.y;
        wa[4] = w2v.x; wa[5] = w2v.y; wa[6] = w3v.x; wa[7] = w3v.y;
    }

    // layer 1
    ull h2[2][HH];
#pragma unroll
    for (int h = 0; h < HH; h++) {
        float4 tj4 = *reinterpret_cast<const float4*>(&s_tjt[h][jl]);
        ull tiv2 = pack2(tiv[h], tiv[h]);
        h2[0][h] = tanh2(fma2(a2lo, wa[h], add2(pack2(tj4.x, tj4.y), tiv2)));
        h2[1][h] = tanh2(fma2(a2hi, wa[h], add2(pack2(tj4.z, tj4.w), tiv2)));
    }

    // layers 2..4: h outer, k inner; 16 independent acc chains
#pragma unroll
    for (int l = 0; l < 3; l++) {
        ull acc[2][HH];
#pragma unroll
        for (int k = 0; k < HH; k += 2) {
            ulonglong2 bk = *reinterpret_cast<const ulonglong2*>(&s_bd[l][k]);
            acc[0][k] = bk.x; acc[1][k] = bk.x;
            acc[0][k + 1] = bk.y; acc[1][k + 1] = bk.y;
        }
#pragma unroll
        for (int h = 0; h < HH; h++) {
            ull hv0 = h2[0][h];
            ull hv1 = h2[1][h];
#pragma unroll
            for (int kp = 0; kp < HH / 2; kp++) {
                ulonglong2 w = *reinterpret_cast<const ulonglong2*>(&s_wd[l][h * HH + kp * 2]);
                acc[0][kp * 2]     = fma2(hv0, w.x, acc[0][kp * 2]);
                acc[1][kp * 2]     = fma2(hv1, w.x, acc[1][kp * 2]);
                acc[0][kp * 2 + 1] = fma2(hv0, w.y, acc[0][kp * 2 + 1]);
                acc[1][kp * 2 + 1] = fma2(hv1, w.y, acc[1][kp * 2 + 1]);
            }
        }
#pragma unroll
        for (int p = 0; p < 2; p++)
#pragma unroll
            for (int k = 0; k < HH; k++)
                h2[p][k] = tanh2(acc[p][k]);
    }

    // output layer: w5 via LDS.128 pairs
    ull o2lo = s_b5d, o2hi = s_b5d;
#pragma unroll
    for (int hp = 0; hp < HH / 2; hp++) {
        ulonglong2 w = *reinterpret_cast<const ulonglong2*>(&s_w5d[hp * 2]);
        o2lo = fma2(h2[0][hp * 2], w.x, o2lo);
        o2hi = fma2(h2[1][hp * 2], w.x, o2hi);
        o2lo = fma2(h2[0][hp * 2 + 1], w.y, o2lo);
        o2hi = fma2(h2[1][hp * 2 + 1], w.y, o2hi);
    }
    float4 o4;
    unpack2(o2lo, o4.x, o4.y);
    unpack2(o2hi, o4.z, o4.w);
    *reinterpret_cast<float4*>(out + off) = o4;
}

// ---------------------------------------------------------------------------
extern "C" void kernel_launch(void* const* d_in, const int* in_sizes, int n_in,
                              void* d_out, int out_size) {
    const float* x  = (const float*)d_in[0];
    const float* A  = (const float*)d_in[1];
    const float* vp = (const float*)d_in[2];
    const float* W1 = (const float*)d_in[3];
    const float* b1 = (const float*)d_in[4];
    const float* W2 = (const float*)d_in[5];
    const float* b2 = (const float*)d_in[6];
    const float* W3 = (const float*)d_in[7];
    const float* b3 = (const float*)d_in[8];
    const float* W4 = (const float*)d_in[9];
    const float* b4 = (const float*)d_in[10];
    const float* W5 = (const float*)d_in[11];
    const float* b5 = (const float*)d_in[12];
    float* out = (float*)d_out;

    dim3 grid(NN / 32, NN / 32, BB);   // 32 x 32 x 2 = 2048 blocks
    edge_mlp_kernel<<<grid, 256>>>(x, A, vp, W1, b1, W2, b2, W3, b3,
                                   W4, b4, W5, b5, out);
}

// round 11
// speedup vs baseline: 1.6030x; 1.4498x over previous
#include <cuda_runtime.h>
#include <cuda_bf16.h>

#define BB 2
#define NN 1024
#define DD 16
#define HH 8
#define W1STRIDE (3 * DD + 1)   // 49

typedef unsigned long long ull;

// ---------------------------------------------------------------------------
// Constant-memory weight pack (constant-bank port, off the l1tex pipe).
// wd[l][h][kp] = ( (w[2kp][h],w[2kp][h]), (w[2kp+1][h],w[2kp+1][h]) )
// ---------------------------------------------------------------------------
struct ConstPack {
    ulonglong2 wd[3][HH][HH / 2];
    ulonglong2 bd[3][HH / 2];
    ull        w5d[HH];
    ull        w1ad[HH];
    ull        b5d;
};
__constant__ ConstPack c_pack;
__device__   ConstPack g_stage;

__device__ __forceinline__ float tanh_approx(float x) {
    float y;
    asm("tanh.approx.f32 %0, %1;" : "=f"(y) : "f"(x));
    return y;
}
__device__ __forceinline__ ull pack2(float lo, float hi) {
    ull d;
    asm("mov.b64 %0, {%1, %2};" : "=l"(d) : "f"(lo), "f"(hi));
    return d;
}
__device__ __forceinline__ void unpack2(ull v, float& lo, float& hi) {
    asm("mov.b64 {%0, %1}, %2;" : "=f"(lo), "=f"(hi) : "l"(v));
}
__device__ __forceinline__ ull fma2(ull a, ull b, ull c) {
    ull d;
    asm("fma.rn.f32x2 %0, %1, %2, %3;" : "=l"(d) : "l"(a), "l"(b), "l"(c));
    return d;
}
__device__ __forceinline__ ull add2(ull a, ull b) {
    ull d;
    asm("add.rn.f32x2 %0, %1, %2;" : "=l"(d) : "l"(a), "l"(b));
    return d;
}
__device__ __forceinline__ ull tanh2(ull v) {
    float lo, hi;
    unpack2(v, lo, hi);
    return pack2(tanh_approx(lo), tanh_approx(hi));
}

// ---------------------------------------------------------------------------
// Prep kernel: pack duplicated-pair weight tables into the staging buffer.
// ---------------------------------------------------------------------------
__global__ void pack_kernel(const float* __restrict__ W1,
                            const float* __restrict__ W2, const float* __restrict__ b2,
                            const float* __restrict__ W3, const float* __restrict__ b3,
                            const float* __restrict__ W4, const float* __restrict__ b4,
                            const float* __restrict__ W5, const float* __restrict__ b5) {
    int t = threadIdx.x;
    if (t < 96) {                       // wd: 3 x 8 x 4
        int l  = t / 32;
        int h  = (t / 4) & 7;
        int kp = t & 3;
        const float* W = (l == 0) ? W2 : (l == 1) ? W3 : W4;
        float w0 = W[(2 * kp)     * HH + h];
        float w1 = W[(2 * kp + 1) * HH + h];
        g_stage.wd[l][h][kp] = make_ulonglong2(pack2(w0, w0), pack2(w1, w1));
    } else if (t < 108) {               // bd: 3 x 4
        int l  = (t - 96) / 4;
        int kp = (t - 96) & 3;
        const float* bb = (l == 0) ? b2 : (l == 1) ? b3 : b4;
        float v0 = bb[2 * kp], v1 = bb[2 * kp + 1];
        g_stage.bd[l][kp] = make_ulonglong2(pack2(v0, v0), pack2(v1, v1));
    } else if (t < 116) {               // w5d
        int h = t - 108;
        float w = W5[h];
        g_stage.w5d[h] = pack2(w, w);
    } else if (t < 124) {               // w1ad
        int h = t - 116;
        float w = W1[h * W1STRIDE + 3 * DD];
        g_stage.w1ad[h] = pack2(w, w);
    } else if (t == 124) {
        float v = b5[0];
        g_stage.b5d = pack2(v, v);
    }
}

// ---------------------------------------------------------------------------
// Main kernel: exact R5 dataflow (32i x 32j, 4 edges/thread, 2 f32x2 lanes,
// h-outer independent accumulators); uniform weight reads from __constant__.
// ---------------------------------------------------------------------------
__global__ __launch_bounds__(256, 3)
void edge_mlp_kernel(const float* __restrict__ x,
                     const float* __restrict__ A,
                     const float* __restrict__ vp,
                     const float* __restrict__ W1, const float* __restrict__ b1,
                     float* __restrict__ out) {
    __shared__ __align__(16) float s_xj[32][DD];
    __shared__ __align__(16) float s_xi[32][DD];
    __shared__ __align__(16) float s_w1[HH * W1STRIDE];
    __shared__ __align__(16) float s_tjt[HH][32];   // t_j transposed [h][j]
    __shared__ __align__(16) float s_ti[32 * HH];   // t_i + t_v + b1, [i][h]

    const int tid = threadIdx.x;
    const int b  = blockIdx.z;
    const int i0 = blockIdx.y * 32;
    const int j0 = blockIdx.x * 32;

    // --- phase 1: stage x rows + W1 into shared ---
    {
        int row = tid >> 2;
        int c4  = (tid & 3) * 4;
        if (row < 32) {
            float4 v = *reinterpret_cast<const float4*>(x + ((size_t)(b * NN + j0 + row)) * DD + c4);
            s_xj[row][c4] = v.x; s_xj[row][c4 + 1] = v.y;
            s_xj[row][c4 + 2] = v.z; s_xj[row][c4 + 3] = v.w;
        } else {
            int r = row - 32;
            float4 v = *reinterpret_cast<const float4*>(x + ((size_t)(b * NN + i0 + r)) * DD + c4);
            s_xi[r][c4] = v.x; s_xi[r][c4 + 1] = v.y;
            s_xi[r][c4 + 2] = v.z; s_xi[r][c4 + 3] = v.w;
        }
        s_w1[tid] = W1[tid];
        if (tid < HH * W1STRIDE - 256) s_w1[256 + tid] = W1[256 + tid];
    }
    __syncthreads();

    const int ii = tid >> 3;         // 0..31
    const int jl = (tid & 7) * 4;    // 0,4,...,28

    const size_t off = ((size_t)(b * NN + i0 + ii)) * NN + j0 + jl;
    float4 a4 = *reinterpret_cast<const float4*>(A + off);

    // --- phase 2: per-row projections ---
    {
        int n = tid >> 3;
        int h = tid & 7;
        const float* wr = s_w1 + h * W1STRIDE;
        float tj = 0.0f, ti = 0.0f;
#pragma unroll
        for (int c = 0; c < DD; c++) {
            tj += s_xj[n][c] * wr[c];
            ti += s_xi[n][c] * wr[DD + c];
        }
        float tv = b1[h];
#pragma unroll
        for (int c = 0; c < DD; c++)
            tv += vp[b * DD + c] * wr[2 * DD + c];
        s_tjt[h][n] = tj;
        s_ti[n * HH + h] = ti + tv;
    }
    __syncthreads();

    // --- phase 3: packed edge MLP (weights from constant bank) ---
    ull a2lo = pack2(a4.x, a4.y);
    ull a2hi = pack2(a4.z, a4.w);

    ull h2[2][HH];
#pragma unroll
    for (int h = 0; h < HH; h++) {
        float4 tj4 = *reinterpret_cast<const float4*>(&s_tjt[h][jl]);
        float tival = s_ti[ii * HH + h];
        ull tiv = pack2(tival, tival);
        ull wa = c_pack.w1ad[h];
        h2[0][h] = tanh2(fma2(a2lo, wa, add2(pack2(tj4.x, tj4.y), tiv)));
        h2[1][h] = tanh2(fma2(a2hi, wa, add2(pack2(tj4.z, tj4.w), tiv)));
    }

#pragma unroll
    for (int l = 0; l < 3; l++) {
        ull acc[2][HH];
#pragma unroll
        for (int kp = 0; kp < HH / 2; kp++) {
            ulonglong2 bk = c_pack.bd[l][kp];
            acc[0][kp * 2] = bk.x; acc[1][kp * 2] = bk.x;
            acc[0][kp * 2 + 1] = bk.y; acc[1][kp * 2 + 1] = bk.y;
        }
#pragma unroll
        for (int h = 0; h < HH; h++) {
            ull hv0 = h2[0][h];
            ull hv1 = h2[1][h];
#pragma unroll
            for (int kp = 0; kp < HH / 2; kp++) {
                ulonglong2 w = c_pack.wd[l][h][kp];
                acc[0][kp * 2]     = fma2(hv0, w.x, acc[0][kp * 2]);
                acc[1][kp * 2]     = fma2(hv1, w.x, acc[1][kp * 2]);
                acc[0][kp * 2 + 1] = fma2(hv0, w.y, acc[0][kp * 2 + 1]);
                acc[1][kp * 2 + 1] = fma2(hv1, w.y, acc[1][kp * 2 + 1]);
            }
        }
#pragma unroll
        for (int p = 0; p < 2; p++)
#pragma unroll
            for (int k = 0; k < HH; k++)
                h2[p][k] = tanh2(acc[p][k]);
    }

    ull o2lo = c_pack.b5d, o2hi = c_pack.b5d;
#pragma unroll
    for (int h = 0; h < HH; h++) {
        ull w = c_pack.w5d[h];
        o2lo = fma2(h2[0][h], w, o2lo);
        o2hi = fma2(h2[1][h], w, o2hi);
    }
    float4 o4;
    unpack2(o2lo, o4.x, o4.y);
    unpack2(o2hi, o4.z, o4.w);
    *reinterpret_cast<float4*>(out + off) = o4;
}

// ---------------------------------------------------------------------------
extern "C" void kernel_launch(void* const* d_in, const int* in_sizes, int n_in,
                              void* d_out, int out_size) {
    const float* x  = (const float*)d_in[0];
    const float* A  = (const float*)d_in[1];
    const float* vp = (const float*)d_in[2];
    const float* W1 = (const float*)d_in[3];
    const float* b1 = (const float*)d_in[4];
    const float* W2 = (const float*)d_in[5];
    const float* b2 = (const float*)d_in[6];
    const float* W3 = (const float*)d_in[7];
    const float* b3 = (const float*)d_in[8];
    const float* W4 = (const float*)d_in[9];
    const float* b4 = (const float*)d_in[10];
    const float* W5 = (const float*)d_in[11];
    const float* b5 = (const float*)d_in[12];
    float* out = (float*)d_out;

    // 1) pack dup-pair tables into the staging buffer (device global)
    pack_kernel<<<1, 128>>>(W1, W2, b2, W3, b3, W4, b4, W5, b5);

    // 2) staging -> __constant__ as a plain D2D memcpy node (capture-safe)
    void* stage_ptr = nullptr;
    void* const_ptr = nullptr;
    cudaGetSymbolAddress(&stage_ptr, g_stage);
    cudaGetSymbolAddress(&const_ptr, c_pack);
    cudaMemcpyAsync(const_ptr, stage_ptr, sizeof(ConstPack),
                    cudaMemcpyDeviceToDevice, 0);

    // 3) main kernel
    dim3 grid(NN / 32, NN / 32, BB);   // 32 x 32 x 2 = 2048 blocks
    edge_mlp_kernel<<<grid, 256>>>(x, A, vp, W1, b1, out);
}